// round 15
// baseline (speedup 1.0000x reference)
#include <cuda_runtime.h>

#define BB 8
#define CC 14
#define HH 512
#define WW 512
#define PP (HH * WW)          // 262144 = 2^18
#define KK 13                 // classes 1..13
#define NBK (BB * KK)         // 104
#define THREADS 256
#define UNITS ((BB * PP / 2) / THREADS)   // 4096 work units (512 px each)
#define GRID_BLOCKS 1024                  // one wave; exactly 4 units/block
#define DEPTH 6               // cp.async pipeline depth (smem-resident)

// Global scratch. Zero-initialized at module load; the last block resets
// them after consuming, so every invocation starts from zeros.
__device__ float        g_kl[NBK];
__device__ unsigned int g_n[NBK];
__device__ unsigned int g_flag[NBK];
__device__ unsigned int g_count;

static __device__ __forceinline__ unsigned int smem_u32(const void* p) {
    unsigned int a;
    asm("{ .reg .u64 t; cvta.to.shared.u64 t, %1; cvt.u32.u64 %0, t; }"
        : "=r"(a) : "l"(p));
    return a;
}

static __device__ __forceinline__ void cp8(unsigned int dst, const float* src) {
    asm volatile("cp.async.ca.shared.global [%0], [%1], 8;"
                 :: "r"(dst), "l"(src) : "memory");
}

static __device__ __forceinline__ void cp_commit() {
    asm volatile("cp.async.commit_group;" ::: "memory");
}

__global__ void __launch_bounds__(THREADS, 7) bkd_fused_kernel(
    const float* __restrict__ S,
    const float* __restrict__ T,
    const int*   __restrict__ gt,
    float*       __restrict__ out)
{
    // Pipeline buffer: per stage, per thread, one float4 = {S.x,S.y,T.x,T.y}
    __shared__ float4       sbuf[DEPTH][THREADS];
    __shared__ float        s_kl[NBK];
    __shared__ unsigned int s_n[NBK];
    __shared__ unsigned int s_flag[NBK];
    __shared__ unsigned int s_isLast;

    if (threadIdx.x < NBK) {
        s_kl[threadIdx.x]   = 0.0f;
        s_n[threadIdx.x]    = 0u;
        s_flag[threadIdx.x] = 0u;
    }
    __syncthreads();   // bins visible; no further barriers until final flush

    // Per-thread smem slot addresses (shared-space u32)
    const unsigned int slotS = smem_u32(&sbuf[0][threadIdx.x].x);
    const unsigned int slotT = smem_u32(&sbuf[0][threadIdx.x].z);
    const unsigned int stageStride = (unsigned int)(THREADS * sizeof(float4));

    // ---- exactly 4 units per block, all blocks resident in one wave ----
    for (int uu = 0; uu < UNITS / GRID_BLOCKS; uu++) {
        const int u   = blockIdx.x + uu * GRID_BLOCKS;
        const int p0  = (u * THREADS + threadIdx.x) << 1;   // 2 px per thread
        const int b   = p0 >> 18;                // / PP
        const int hw  = p0 & (PP - 1);
        const int h   = hw >> 9;                 // / 512
        const int w   = hw & 511;

        const float* Sp = S + (size_t)b * CC * PP + hw;
        const float* Tp = T + (size_t)b * CC * PP + hw;

        // ---- prime: async-issue first DEPTH channels (one group each) ----
#pragma unroll
        for (int i = 0; i < DEPTH; i++) {
            cp8(slotS + i * stageStride, Sp + (size_t)i * PP);
            cp8(slotT + i * stageStride, Tp + (size_t)i * PP);
            cp_commit();
        }

        // ---- boundary detection (plain LDG, overlaps cp.async flight) ----
        const int* gtb = gt + (size_t)b * PP;
        int2 gc = *(const int2*)(gtb + hw);
        int2 gu = (h > 0)      ? *(const int2*)(gtb + hw - WW) : make_int2(-1, -1);
        int2 gd = (h < HH - 1) ? *(const int2*)(gtb + hw + WW) : make_int2(-1, -1);
        int gl = (w > 0)       ? gtb[hw - 1] : -1;
        int gr = (w + 2 < WW)  ? gtb[hw + 2] : -1;

        const bool bnd0 = (gc.x >= 1) &&
                          (gu.x != gc.x || gd.x != gc.x || gl   != gc.x || gc.y != gc.x);
        const bool bnd1 = (gc.y >= 1) &&
                          (gu.y != gc.y || gd.y != gc.y || gc.x != gc.y || gr   != gc.y);

        // ---- self-timed per-thread pipeline over 14 channels ----
        // Invariant at loop top: DEPTH groups pending (channels c..c+DEPTH-1,
        // tail groups may be empty). wait_group DEPTH-1 retires channel c's
        // group (retirement is in commit order). READ the slot into registers
        // BEFORE issuing the overwriting prefetch — this ordering is the
        // correctness fix vs R14.
        float ZS0 = 0.f, ZS1 = 0.f;
        float ZT0 = 0.f, ZT1 = 0.f;
        float A0  = 0.f, A1  = 0.f;

#pragma unroll
        for (int c = 0; c < CC; c++) {
            asm volatile("cp.async.wait_group %0;" :: "n"(DEPTH - 1) : "memory");

            float4 v = sbuf[c % DEPTH][threadIdx.x];    // {Sx,Sy,Tx,Ty}

            // prefetch channel c+DEPTH into the just-freed slot (value of v
            // is already register-resident; LDGSTS write lands >=L2 latency
            // after the LDS issued above)
            if (c + DEPTH < CC) {
                const int slot = c % DEPTH;
                cp8(slotS + slot * stageStride, Sp + (size_t)(c + DEPTH) * PP);
                cp8(slotT + slot * stageStride, Tp + (size_t)(c + DEPTH) * PP);
            }
            cp_commit();   // possibly-empty group keeps pending count exact

            float es0 = __expf(v.x), et0 = __expf(v.z);
            float es1 = __expf(v.y), et1 = __expf(v.w);
            ZS0 += es0; ZT0 += et0; A0 = fmaf(et0, v.z - v.x, A0);
            ZS1 += es1; ZT1 += et1; A1 = fmaf(et1, v.w - v.y, A1);
        }

        // ---- accumulate into per-block [b,k] bins (no barriers) ----
        if (bnd0) {
            float r  = __fdividef(1.0f, ZT0);
            float kl = A0 * r + __logf(ZS0 * r);
            int idx = b * KK + (gc.x - 1);
            atomicAdd(&s_kl[idx], kl);
            atomicAdd(&s_n[idx], 1u);
            if (hw > 0) s_flag[idx] = 1u;         // idempotent racing write
        }
        if (bnd1) {
            float r  = __fdividef(1.0f, ZT1);
            float kl = A1 * r + __logf(ZS1 * r);
            int idx = b * KK + (gc.y - 1);
            atomicAdd(&s_kl[idx], kl);
            atomicAdd(&s_n[idx], 1u);
            s_flag[idx] = 1u;                     // hw+1 > 0 always
        }
    }

    // ---- single flush of per-block bins to global accumulators ----
    __syncthreads();
    if (threadIdx.x < NBK) {
        int idx = threadIdx.x;
        if (s_n[idx] > 0u) {
            atomicAdd(&g_kl[idx], s_kl[idx]);
            atomicAdd(&g_n[idx],  s_n[idx]);
        }
        if (s_flag[idx]) atomicOr(&g_flag[idx], 1u);
    }

    // ---- last-block-done finalize (fused reduction + scratch reset) ----
    __threadfence();
    if (threadIdx.x == 0) {
        unsigned int v = atomicAdd(&g_count, 1u);
        s_isLast = (v == (unsigned int)(GRID_BLOCKS - 1)) ? 1u : 0u;
    }
    __syncthreads();

    if (s_isLast) {
        float* sred = (float*)&sbuf[0][0];        // reuse stage 0 as scratch
        int i = threadIdx.x;
        float t = 0.0f;
        if (i < NBK && g_flag[i]) {
            unsigned int n = g_n[i];
            if (n < 1u) n = 1u;
            t = g_kl[i] / (14.0f * (float)n);
        }
        sred[i] = t;
        __syncthreads();
#pragma unroll
        for (int s = 128; s > 0; s >>= 1) {
            if (i < s) sred[i] += sred[i + s];
            __syncthreads();
        }
        if (i == 0) {
            out[0] = sred[0];        // LOSS_WEIGHT * TAU^2 == 1
            g_count = 0u;            // reset for next replay
        }
        if (i < NBK) {
            g_kl[i]   = 0.0f;
            g_n[i]    = 0u;
            g_flag[i] = 0u;
        }
    }
}

extern "C" void kernel_launch(void* const* d_in, const int* in_sizes, int n_in,
                              void* d_out, int out_size) {
    const float* S  = (const float*)d_in[0];
    const float* T  = (const float*)d_in[1];
    const int*   gt = (const int*)d_in[2];
    float* out = (float*)d_out;

    bkd_fused_kernel<<<GRID_BLOCKS, THREADS>>>(S, T, gt, out);
}

// round 16
// speedup vs baseline: 1.1651x; 1.1651x over previous
#include <cuda_runtime.h>

#define BB 8
#define CC 14
#define HH 512
#define WW 512
#define PP (HH * WW)          // 262144 = 2^18
#define KK 13                 // classes 1..13
#define NBK (BB * KK)         // 104
#define THREADS 256
#define UNITS ((BB * PP / 2) / THREADS)   // 4096 work units (512 px each)
#define GRID_BLOCKS (152 * 8)             // 1216: full residency, one wave
#define DEPTH 3               // software-pipeline depth (channels prefetched)

// Global scratch. Zero-initialized at module load; the last block resets
// them after consuming, so every invocation starts from zeros.
__device__ float        g_kl[NBK];
__device__ unsigned int g_n[NBK];
__device__ unsigned int g_flag[NBK];
__device__ unsigned int g_count;
__device__ unsigned int g_unit;    // work-stealing cursor

__global__ void __launch_bounds__(THREADS, 7) bkd_fused_kernel(
    const float* __restrict__ S,
    const float* __restrict__ T,
    const int*   __restrict__ gt,
    float*       __restrict__ out)
{
    __shared__ float        s_kl[KK];
    __shared__ unsigned int s_n[KK];
    __shared__ unsigned int s_flag[KK];
    __shared__ unsigned int s_next;
    __shared__ unsigned int s_isLast;

    // ---- work-stealing unit loop: first unit static, rest stolen ----
    int u = blockIdx.x;
    while (u < UNITS) {
        // zero per-unit class bins
        if (threadIdx.x < KK) {
            s_kl[threadIdx.x]   = 0.0f;
            s_n[threadIdx.x]    = 0u;
            s_flag[threadIdx.x] = 0u;
        }
        __syncthreads();   // zeros visible

        const int p0  = (u * THREADS + threadIdx.x) << 1;   // 2 px per thread
        const int b   = p0 >> 18;                // / PP
        const int hw  = p0 & (PP - 1);
        const int h   = hw >> 9;                 // / 512
        const int w   = hw & 511;

        const float* Sp = S + (size_t)b * CC * PP + hw;
        const float* Tp = T + (size_t)b * CC * PP + hw;

        // ---- prime the pipeline: first DEPTH channels ----
        float2 bs[DEPTH], bt[DEPTH];
#pragma unroll
        for (int i = 0; i < DEPTH; i++) {
            bs[i] = __ldcs((const float2*)(Sp + (size_t)i * PP));
            bt[i] = __ldcs((const float2*)(Tp + (size_t)i * PP));
        }

        // steal the next unit while loads are in flight (warp 2, no
        // conflict with bin writers in warp 0)
        if (threadIdx.x == 64)
            s_next = (unsigned int)GRID_BLOCKS + atomicAdd(&g_unit, 1u);

        // ---- boundary detection (overlaps with in-flight S/T loads) ----
        const int* gtb = gt + (size_t)b * PP;
        int2 gc = *(const int2*)(gtb + hw);
        int2 gu = (h > 0)      ? *(const int2*)(gtb + hw - WW) : make_int2(-1, -1);
        int2 gd = (h < HH - 1) ? *(const int2*)(gtb + hw + WW) : make_int2(-1, -1);
        int gl = (w > 0)       ? gtb[hw - 1] : -1;
        int gr = (w + 2 < WW)  ? gtb[hw + 2] : -1;

        const bool bnd0 = (gc.x >= 1) &&
                          (gu.x != gc.x || gd.x != gc.x || gl   != gc.x || gc.y != gc.x);
        const bool bnd1 = (gc.y >= 1) &&
                          (gu.y != gc.y || gd.y != gc.y || gc.x != gc.y || gr   != gc.y);

        // ---- pipelined single-pass softmax/KL accumulation ----
        // kl = A/Z_T + log(Z_S/Z_T)
        float ZS0 = 0.f, ZS1 = 0.f;
        float ZT0 = 0.f, ZT1 = 0.f;
        float A0  = 0.f, A1  = 0.f;

#pragma unroll
        for (int c = 0; c < CC; c++) {
            const int slot = c % DEPTH;           // constant after full unroll
            float2 xs = bs[slot];
            float2 xt = bt[slot];
            if (c + DEPTH < CC) {                 // issue next loads BEFORE compute
                bs[slot] = __ldcs((const float2*)(Sp + (size_t)(c + DEPTH) * PP));
                bt[slot] = __ldcs((const float2*)(Tp + (size_t)(c + DEPTH) * PP));
            }
            float es0 = __expf(xs.x), et0 = __expf(xt.x);
            float es1 = __expf(xs.y), et1 = __expf(xt.y);
            ZS0 += es0; ZT0 += et0; A0 = fmaf(et0, xt.x - xs.x, A0);
            ZS1 += es1; ZT1 += et1; A1 = fmaf(et1, xt.y - xs.y, A1);
        }

        // ---- per-unit shared accumulation into 13 class bins ----
        if (bnd0) {
            float r  = __fdividef(1.0f, ZT0);
            float kl = A0 * r + __logf(ZS0 * r);
            int k = gc.x - 1;
            atomicAdd(&s_kl[k], kl);
            atomicAdd(&s_n[k], 1u);
            if (hw > 0) s_flag[k] = 1u;           // idempotent racing write
        }
        if (bnd1) {
            float r  = __fdividef(1.0f, ZT1);
            float kl = A1 * r + __logf(ZS1 * r);
            int k = gc.y - 1;
            atomicAdd(&s_kl[k], kl);
            atomicAdd(&s_n[k], 1u);
            s_flag[k] = 1u;                        // hw+1 > 0 always
        }
        __syncthreads();   // accumulation done; s_next visible

        // flush unit bins to global [b,k] accumulators
        if (threadIdx.x < KK) {
            int k   = threadIdx.x;
            int idx = b * KK + k;
            if (s_n[k] > 0u) {
                atomicAdd(&g_kl[idx], s_kl[k]);
                atomicAdd(&g_n[idx],  s_n[k]);
            }
            if (s_flag[k]) atomicOr(&g_flag[idx], 1u);
        }

        // read next unit (written before the sync above; the next write by
        // tid 64 happens only after every thread passes the loop-top sync)
        u = (int)s_next;
    }

    // ---- last-block-done finalize (fused reduction + scratch reset) ----
    __threadfence();
    if (threadIdx.x == 0) {
        unsigned int v = atomicAdd(&g_count, 1u);
        s_isLast = (v == (unsigned int)(GRID_BLOCKS - 1)) ? 1u : 0u;
    }
    __syncthreads();

    if (s_isLast) {
        __shared__ float sred[256];
        int i = threadIdx.x;
        float t = 0.0f;
        if (i < NBK && g_flag[i]) {
            unsigned int n = g_n[i];
            if (n < 1u) n = 1u;
            t = g_kl[i] / (14.0f * (float)n);
        }
        sred[i] = t;
        __syncthreads();
#pragma unroll
        for (int s = 128; s > 0; s >>= 1) {
            if (i < s) sred[i] += sred[i + s];
            __syncthreads();
        }
        if (i == 0) {
            out[0] = sred[0];        // LOSS_WEIGHT * TAU^2 == 1
            g_count = 0u;            // reset for next replay
            g_unit  = 0u;
        }
        if (i < NBK) {
            g_kl[i]   = 0.0f;
            g_n[i]    = 0u;
            g_flag[i] = 0u;
        }
    }
}

extern "C" void kernel_launch(void* const* d_in, const int* in_sizes, int n_in,
                              void* d_out, int out_size) {
    const float* S  = (const float*)d_in[0];
    const float* T  = (const float*)d_in[1];
    const int*   gt = (const int*)d_in[2];
    float* out = (float*)d_out;

    bkd_fused_kernel<<<GRID_BLOCKS, THREADS>>>(S, T, gt, out);
}